// round 2
// baseline (speedup 1.0000x reference)
#include <cuda_runtime.h>
#include <cuda_bf16.h>

#define BB 8
#define NN 2048
#define DD 64
#define TI 64
#define TJ 64

// __device__ scratch (no allocations allowed)
__device__ float g_h[BB * NN * DD];        // h_ope, fp32
__device__ float g_s[BB * NN];             // exp(a_src)
__device__ float g_t[BB * NN];             // exp(a_dst)
__device__ float g_u[BB * NN];             // exp(0.2*a_src)
__device__ float g_v[BB * NN];             // exp(0.2*a_dst)
__device__ float g_lam[2 * DD];            // lambda_adj[64], lambda_job[64]

// ---- packed f32x2 helpers (Blackwell FFMA2) ----
__device__ __forceinline__ unsigned long long splat2(float x) {
    unsigned long long r;
    asm("mov.b64 %0, {%1, %1};" : "=l"(r) : "f"(x));
    return r;
}
__device__ __forceinline__ void fma2(unsigned long long& d, unsigned long long a, unsigned long long b) {
    asm("fma.rn.f32x2 %0, %1, %2, %0;" : "+l"(d) : "l"(a), "l"(b));
}
__device__ __forceinline__ void add2(unsigned long long& d, unsigned long long a) {
    asm("add.rn.f32x2 %0, %0, %1;" : "+l"(d) : "l"(a));
}
__device__ __forceinline__ float2 unpack2(unsigned long long v) {
    float2 f;
    asm("mov.b64 {%0, %1}, %2;" : "=f"(f.x), "=f"(f.y) : "l"(v));
    return f;
}

// =====================================================================
// Kernel A: h = feats @ W^T, a_src/a_dst exps, lambdas
// 512 threads, 8 rows per block, grid = B*N/8
// =====================================================================
__global__ __launch_bounds__(512) void prep_kernel(
    const float* __restrict__ feats, const float* __restrict__ W,
    const float* __restrict__ attn_src, const float* __restrict__ attn_dst,
    const float* __restrict__ lambda_params)
{
    __shared__ float sWt[DD * DD];   // W transposed: sWt[d*64+o]
    __shared__ float sF[8][DD];
    __shared__ float sRs[512];
    __shared__ float sRd[512];

    const int t = threadIdx.x;
    const int o = t & 63;
    const int r = t >> 6;
    const int row0 = blockIdx.x * 8;

    #pragma unroll
    for (int w = 0; w < 8; ++w) {
        int x = t + 512 * w;
        sWt[(x & 63) * DD + (x >> 6)] = W[x];
    }
    sF[r][o] = feats[(size_t)(row0 + r) * DD + o];
    __syncthreads();

    float h = 0.0f;
    #pragma unroll
    for (int d = 0; d < DD; ++d) h = fmaf(sF[r][d], sWt[d * DD + o], h);

    g_h[(size_t)(row0 + r) * DD + o] = h;
    sRs[t] = h * attn_src[o];
    sRd[t] = h * attn_dst[o];
    __syncthreads();

    #pragma unroll
    for (int s = 32; s > 0; s >>= 1) {
        if (o < s) { sRs[t] += sRs[t + s]; sRd[t] += sRd[t + s]; }
        __syncthreads();
    }
    if (o == 0) {
        float as = sRs[t], ad = sRd[t];
        int n = row0 + r;
        g_s[n] = expf(as);
        g_u[n] = expf(0.2f * as);
        g_t[n] = expf(ad);
        g_v[n] = expf(0.2f * ad);
    }
    if (blockIdx.x == 0 && t < DD) {
        float l0 = lambda_params[t * 2];
        float l1 = lambda_params[t * 2 + 1];
        float m = fmaxf(l0, l1);
        float e0 = expf(l0 - m), e1 = expf(l1 - m);
        float inv = 1.0f / (e0 + e1);
        g_lam[t] = e0 * inv;
        g_lam[DD + t] = e1 * inv;
    }
}

// =====================================================================
// Kernel B: masked dual-softmax attention + aggregation + blend
// grid = (N/TI, B), 128 threads; thread tile = 4 i x 8 d, FFMA2 packed over i
// =====================================================================
__global__ __launch_bounds__(128, 4) void attn_kernel(
    const int* __restrict__ mask_adj, const int* __restrict__ mask_job,
    const int* __restrict__ bidx,
    const float* __restrict__ feats, float* __restrict__ out)
{
    // P tiles: [j][i-pair], XOR-swizzled over pair index, stored as float2 (i0,i1)
    __shared__ float2 sPa[TJ * 32];
    __shared__ float2 sPj[TJ * 32];
    __shared__ float sSi[TI], sUi[TI];
    __shared__ float sDenA[TI], sDenJ[TI];

    const int t = threadIdx.x;
    const int b = blockIdx.y;
    const int i_base = blockIdx.x * TI;
    const int bN = b * NN;

    // batch_idxes is arange(B) by construction (identity gather in the
    // reference). JAX x64 is off so dtype is int32 in practice; read as
    // int32 and clamp so a dtype surprise can never take us out of bounds.
    int mb = bidx[b];
    if (mb < 0 || mb >= BB) mb = b;

    // phase-2 identity
    const int dg = t & 7;    // d-group: d = dg*8 .. dg*8+7
    const int ig = t >> 3;   // i-group: i = ig*4 .. ig*4+3 (0..15)
    // phase-1 identity
    const int jj = t & 63;
    const int kh = t >> 6;   // 0/1: pair-index offset

    if (t < TI) {
        sSi[t] = g_s[bN + i_base + t];
        sUi[t] = g_u[bN + i_base + t];
    }

    const int* maB = mask_adj + ((size_t)mb * NN + i_base) * NN;
    const int* mjB = mask_job + ((size_t)mb * NN + i_base) * NN;

    unsigned long long accA[2][8], accJ[2][8];
    #pragma unroll
    for (int r = 0; r < 2; ++r)
        #pragma unroll
        for (int c = 0; c < 8; ++c) { accA[r][c] = 0ull; accJ[r][c] = 0ull; }
    unsigned long long dA0 = 0, dA1 = 0, dJ0 = 0, dJ1 = 0;

    for (int jt = 0; jt < NN / TJ; ++jt) {
        const int jb = jt * TJ;
        __syncthreads();   // previous phase-2 reads done (also covers sSi init)

        // ---- phase 1: build masked P tiles ----
        const float tj = g_t[bN + jb + jj];
        const float vj = g_v[bN + jb + jj];
        const int* maP = maB + jb + jj;
        const int* mjP = mjB + jb + jj;
        #pragma unroll 4
        for (int m = 0; m < 16; ++m) {
            const int k = kh + 2 * m;      // pair index 0..31
            const int i0 = 2 * k;
            const int m_a0 = maP[(size_t)i0 * NN];
            const int m_a1 = maP[(size_t)(i0 + 1) * NN];
            const int m_j0 = mjP[(size_t)i0 * NN];
            const int m_j1 = mjP[(size_t)(i0 + 1) * NN];
            const float st0 = sSi[i0] * tj,     uv0 = sUi[i0] * vj;
            const float st1 = sSi[i0 + 1] * tj, uv1 = sUi[i0 + 1] * vj;
            // exp(leaky(x)): x>=0 <=> exp(x)=s*t >= 1
            const float p0 = (st0 >= 1.0f) ? st0 : uv0;
            const float p1 = (st1 >= 1.0f) ? st1 : uv1;
            const int sw = k ^ (jj & 31);
            sPa[jj * 32 + sw] = make_float2(m_a0 ? p0 : 0.0f, m_a1 ? p1 : 0.0f);
            sPj[jj * 32 + sw] = make_float2(m_j0 ? p0 : 0.0f, m_j1 ? p1 : 0.0f);
        }
        __syncthreads();

        // ---- phase 2: acc += P^T(masked) * h ----
        const float4* hBase = (const float4*)(g_h + ((size_t)(bN + jb) << 6)) + (dg << 1);
        #pragma unroll 2
        for (int j = 0; j < TJ; ++j) {
            const int sw = j & 31;
            const float2* rowA = sPa + j * 32;
            const float2* rowJ = sPj + j * 32;
            unsigned long long pa01 = *(const unsigned long long*)(rowA + ((2 * ig) ^ sw));
            unsigned long long pa23 = *(const unsigned long long*)(rowA + ((2 * ig + 1) ^ sw));
            unsigned long long pj01 = *(const unsigned long long*)(rowJ + ((2 * ig) ^ sw));
            unsigned long long pj23 = *(const unsigned long long*)(rowJ + ((2 * ig + 1) ^ sw));
            const float4 h0 = hBase[j * 16];
            const float4 h1 = hBase[j * 16 + 1];
            unsigned long long H[8];
            H[0] = splat2(h0.x); H[1] = splat2(h0.y); H[2] = splat2(h0.z); H[3] = splat2(h0.w);
            H[4] = splat2(h1.x); H[5] = splat2(h1.y); H[6] = splat2(h1.z); H[7] = splat2(h1.w);
            #pragma unroll
            for (int c = 0; c < 8; ++c) {
                fma2(accA[0][c], pa01, H[c]);
                fma2(accA[1][c], pa23, H[c]);
                fma2(accJ[0][c], pj01, H[c]);
                fma2(accJ[1][c], pj23, H[c]);
            }
            if (dg == 0) { add2(dA0, pa01); add2(dA1, pa23); add2(dJ0, pj01); add2(dJ1, pj23); }
        }
    }

    // ---- epilogue ----
    if (dg == 0) {
        float2 a0 = unpack2(dA0), a1 = unpack2(dA1);
        float2 j0 = unpack2(dJ0), j1 = unpack2(dJ1);
        sDenA[ig * 4 + 0] = a0.x; sDenA[ig * 4 + 1] = a0.y;
        sDenA[ig * 4 + 2] = a1.x; sDenA[ig * 4 + 3] = a1.y;
        sDenJ[ig * 4 + 0] = j0.x; sDenJ[ig * 4 + 1] = j0.y;
        sDenJ[ig * 4 + 2] = j1.x; sDenJ[ig * 4 + 3] = j1.y;
    }
    __syncthreads();

    const float4 lA0 = *(const float4*)&g_lam[dg * 8];
    const float4 lA1 = *(const float4*)&g_lam[dg * 8 + 4];
    const float4 lJ0 = *(const float4*)&g_lam[DD + dg * 8];
    const float4 lJ1 = *(const float4*)&g_lam[DD + dg * 8 + 4];

    #pragma unroll
    for (int r = 0; r < 4; ++r) {
        const int i = i_base + ig * 4 + r;
        const float ra = 1.0f / sDenA[ig * 4 + r];
        const float rj = 1.0f / sDenJ[ig * 4 + r];
        float oA[8], oJ[8];
        #pragma unroll
        for (int c = 0; c < 8; ++c) {
            float2 va = unpack2(accA[r >> 1][c]);
            float2 vb = unpack2(accJ[r >> 1][c]);
            oA[c] = (r & 1) ? va.y : va.x;
            oJ[c] = (r & 1) ? vb.y : vb.x;
        }
        const float* fp = feats + ((size_t)(bN + i) << 6) + dg * 8;
        float* op = out + ((size_t)(bN + i) << 6) + dg * 8;
        const float4 f0 = *(const float4*)fp;
        const float4 f1 = *(const float4*)(fp + 4);
        float4 o0, o1;
        o0.x = lA0.x * oA[0] * ra + lJ0.x * oJ[0] * rj + f0.x;
        o0.y = lA0.y * oA[1] * ra + lJ0.y * oJ[1] * rj + f0.y;
        o0.z = lA0.z * oA[2] * ra + lJ0.z * oJ[2] * rj + f0.z;
        o0.w = lA0.w * oA[3] * ra + lJ0.w * oJ[3] * rj + f0.w;
        o1.x = lA1.x * oA[4] * ra + lJ1.x * oJ[4] * rj + f1.x;
        o1.y = lA1.y * oA[5] * ra + lJ1.y * oJ[5] * rj + f1.y;
        o1.z = lA1.z * oA[6] * ra + lJ1.z * oJ[6] * rj + f1.z;
        o1.w = lA1.w * oA[7] * ra + lJ1.w * oJ[7] * rj + f1.w;
        *(float4*)op = o0;
        *(float4*)(op + 4) = o1;
    }
}

extern "C" void kernel_launch(void* const* d_in, const int* in_sizes, int n_in,
                              void* d_out, int out_size) {
    (void)in_sizes; (void)n_in; (void)out_size;
    const int*   mask_adj      = (const int*)d_in[0];
    const int*   mask_job      = (const int*)d_in[1];
    const int*   bidx          = (const int*)d_in[2];
    const float* feats         = (const float*)d_in[3];
    const float* W             = (const float*)d_in[4];
    const float* attn_src      = (const float*)d_in[5];
    const float* attn_dst      = (const float*)d_in[6];
    const float* lambda_params = (const float*)d_in[7];
    float* out = (float*)d_out;

    prep_kernel<<<BB * NN / 8, 512>>>(feats, W, attn_src, attn_dst, lambda_params);
    attn_kernel<<<dim3(NN / TI, BB), 128>>>(mask_adj, mask_job, bidx, feats, out);
}

// round 3
// speedup vs baseline: 1.7147x; 1.7147x over previous
#include <cuda_runtime.h>
#include <cuda_bf16.h>

#define BB 8
#define NN 2048
#define DD 64
#define TI 64
#define TJ 64
#define SPLIT 4
#define JT_PER_SPLIT (NN / TJ / SPLIT)   // 8 j-tiles per split

// __device__ scratch (no allocations allowed)
__device__ float g_h[BB * NN * DD];        // h_ope, fp32
__device__ float g_s[BB * NN];             // exp(a_src)
__device__ float g_t[BB * NN];             // exp(a_dst)
__device__ float g_u[BB * NN];             // exp(0.2*a_src)
__device__ float g_v[BB * NN];             // exp(0.2*a_dst)
__device__ float g_lam[2 * DD];            // lambda_adj[64], lambda_job[64]

// split-K partial results
__device__ float g_accA[SPLIT][BB * NN * DD];
__device__ float g_accJ[SPLIT][BB * NN * DD];
__device__ float g_denA[SPLIT][BB * NN];
__device__ float g_denJ[SPLIT][BB * NN];

// ---- packed f32x2 helpers (Blackwell FFMA2) ----
__device__ __forceinline__ unsigned long long splat2(float x) {
    unsigned long long r;
    asm("mov.b64 %0, {%1, %1};" : "=l"(r) : "f"(x));
    return r;
}
__device__ __forceinline__ void fma2(unsigned long long& d, unsigned long long a, unsigned long long b) {
    asm("fma.rn.f32x2 %0, %1, %2, %0;" : "+l"(d) : "l"(a), "l"(b));
}
__device__ __forceinline__ void add2(unsigned long long& d, unsigned long long a) {
    asm("add.rn.f32x2 %0, %0, %1;" : "+l"(d) : "l"(a));
}
__device__ __forceinline__ float2 unpack2(unsigned long long v) {
    float2 f;
    asm("mov.b64 {%0, %1}, %2;" : "=f"(f.x), "=f"(f.y) : "l"(v));
    return f;
}

// =====================================================================
// Kernel A: h = feats @ W^T, a_src/a_dst exps, lambdas
// =====================================================================
__global__ __launch_bounds__(512) void prep_kernel(
    const float* __restrict__ feats, const float* __restrict__ W,
    const float* __restrict__ attn_src, const float* __restrict__ attn_dst,
    const float* __restrict__ lambda_params)
{
    __shared__ float sWt[DD * DD];   // W transposed: sWt[d*64+o]
    __shared__ float sF[8][DD];
    __shared__ float sRs[512];
    __shared__ float sRd[512];

    const int t = threadIdx.x;
    const int o = t & 63;
    const int r = t >> 6;
    const int row0 = blockIdx.x * 8;

    #pragma unroll
    for (int w = 0; w < 8; ++w) {
        int x = t + 512 * w;
        sWt[(x & 63) * DD + (x >> 6)] = W[x];
    }
    sF[r][o] = feats[(size_t)(row0 + r) * DD + o];
    __syncthreads();

    float h = 0.0f;
    #pragma unroll
    for (int d = 0; d < DD; ++d) h = fmaf(sF[r][d], sWt[d * DD + o], h);

    g_h[(size_t)(row0 + r) * DD + o] = h;
    sRs[t] = h * attn_src[o];
    sRd[t] = h * attn_dst[o];
    __syncthreads();

    #pragma unroll
    for (int s = 32; s > 0; s >>= 1) {
        if (o < s) { sRs[t] += sRs[t + s]; sRd[t] += sRd[t + s]; }
        __syncthreads();
    }
    if (o == 0) {
        float as = sRs[t], ad = sRd[t];
        int n = row0 + r;
        g_s[n] = expf(as);
        g_u[n] = expf(0.2f * as);
        g_t[n] = expf(ad);
        g_v[n] = expf(0.2f * ad);
    }
    if (blockIdx.x == 0 && t < DD) {
        float l0 = lambda_params[t * 2];
        float l1 = lambda_params[t * 2 + 1];
        float m = fmaxf(l0, l1);
        float e0 = expf(l0 - m), e1 = expf(l1 - m);
        float inv = 1.0f / (e0 + e1);
        g_lam[t] = e0 * inv;
        g_lam[DD + t] = e1 * inv;
    }
}

// =====================================================================
// Kernel B: split-K masked dual-softmax partial sums
// grid = (N/TI, B, SPLIT), 128 threads; thread tile = 4 i x 8 d, FFMA2
// =====================================================================
__global__ __launch_bounds__(128, 4) void attn_split_kernel(
    const int* __restrict__ mask_adj, const int* __restrict__ mask_job,
    const int* __restrict__ bidx)
{
    __shared__ float2 sPa[TJ * 32];
    __shared__ float2 sPj[TJ * 32];
    __shared__ float sSi[TI], sUi[TI];

    const int t = threadIdx.x;
    const int b = blockIdx.y;
    const int sp = blockIdx.z;
    const int i_base = blockIdx.x * TI;
    const int bN = b * NN;

    // batch_idxes is arange(B) (identity gather); clamp defensively
    int mb = bidx[b];
    if (mb < 0 || mb >= BB) mb = b;

    const int dg = t & 7;    // d-group
    const int ig = t >> 3;   // i-group (0..15)
    const int jj = t & 63;
    const int kh = t >> 6;

    if (t < TI) {
        sSi[t] = g_s[bN + i_base + t];
        sUi[t] = g_u[bN + i_base + t];
    }

    const int* maB = mask_adj + ((size_t)mb * NN + i_base) * NN;
    const int* mjB = mask_job + ((size_t)mb * NN + i_base) * NN;

    unsigned long long accA[2][8], accJ[2][8];
    #pragma unroll
    for (int r = 0; r < 2; ++r)
        #pragma unroll
        for (int c = 0; c < 8; ++c) { accA[r][c] = 0ull; accJ[r][c] = 0ull; }
    unsigned long long dA0 = 0, dA1 = 0, dJ0 = 0, dJ1 = 0;

    const int jt0 = sp * JT_PER_SPLIT;
    for (int jt = jt0; jt < jt0 + JT_PER_SPLIT; ++jt) {
        const int jb = jt * TJ;
        __syncthreads();

        // ---- phase 1: build masked P tiles ----
        const float tj = g_t[bN + jb + jj];
        const float vj = g_v[bN + jb + jj];
        const int* maP = maB + jb + jj;
        const int* mjP = mjB + jb + jj;
        #pragma unroll 8
        for (int m = 0; m < 16; ++m) {
            const int k = kh + 2 * m;
            const int i0 = 2 * k;
            const int m_a0 = maP[(size_t)i0 * NN];
            const int m_a1 = maP[(size_t)(i0 + 1) * NN];
            const int m_j0 = mjP[(size_t)i0 * NN];
            const int m_j1 = mjP[(size_t)(i0 + 1) * NN];
            const float st0 = sSi[i0] * tj,     uv0 = sUi[i0] * vj;
            const float st1 = sSi[i0 + 1] * tj, uv1 = sUi[i0 + 1] * vj;
            const float p0 = (st0 >= 1.0f) ? st0 : uv0;   // exp(leaky(e))
            const float p1 = (st1 >= 1.0f) ? st1 : uv1;
            const int sw = k ^ (jj & 31);
            sPa[jj * 32 + sw] = make_float2(m_a0 ? p0 : 0.0f, m_a1 ? p1 : 0.0f);
            sPj[jj * 32 + sw] = make_float2(m_j0 ? p0 : 0.0f, m_j1 ? p1 : 0.0f);
        }
        __syncthreads();

        // ---- phase 2: acc += P^T * h ----
        const float4* hBase = (const float4*)(g_h + ((size_t)(bN + jb) << 6)) + (dg << 1);
        #pragma unroll 2
        for (int j = 0; j < TJ; ++j) {
            const int o0 = (2 * ig) ^ (j & 31);
            const int o1 = o0 ^ 1;
            const float2* rowA = sPa + j * 32;
            const float2* rowJ = sPj + j * 32;
            unsigned long long pa01 = *(const unsigned long long*)(rowA + o0);
            unsigned long long pa23 = *(const unsigned long long*)(rowA + o1);
            unsigned long long pj01 = *(const unsigned long long*)(rowJ + o0);
            unsigned long long pj23 = *(const unsigned long long*)(rowJ + o1);
            const float4 h0 = hBase[j * 16];
            const float4 h1 = hBase[j * 16 + 1];
            unsigned long long H[8];
            H[0] = splat2(h0.x); H[1] = splat2(h0.y); H[2] = splat2(h0.z); H[3] = splat2(h0.w);
            H[4] = splat2(h1.x); H[5] = splat2(h1.y); H[6] = splat2(h1.z); H[7] = splat2(h1.w);
            #pragma unroll
            for (int c = 0; c < 8; ++c) {
                fma2(accA[0][c], pa01, H[c]);
                fma2(accA[1][c], pa23, H[c]);
                fma2(accJ[0][c], pj01, H[c]);
                fma2(accJ[1][c], pj23, H[c]);
            }
            if (dg == 0) { add2(dA0, pa01); add2(dA1, pa23); add2(dJ0, pj01); add2(dJ1, pj23); }
        }
    }

    // ---- epilogue: write partial sums to scratch ----
    if (dg == 0) {
        float2 a0 = unpack2(dA0), a1 = unpack2(dA1);
        float2 j0 = unpack2(dJ0), j1 = unpack2(dJ1);
        int nb = bN + i_base + ig * 4;
        g_denA[sp][nb + 0] = a0.x; g_denA[sp][nb + 1] = a0.y;
        g_denA[sp][nb + 2] = a1.x; g_denA[sp][nb + 3] = a1.y;
        g_denJ[sp][nb + 0] = j0.x; g_denJ[sp][nb + 1] = j0.y;
        g_denJ[sp][nb + 2] = j1.x; g_denJ[sp][nb + 3] = j1.y;
    }

    #pragma unroll
    for (int r = 0; r < 4; ++r) {
        const int i = i_base + ig * 4 + r;
        float4 oA0, oA1, oJ0, oJ1;
        float* pA = (float*)&oA0;   // oA0/oA1 contiguous? build explicitly instead
        (void)pA;
        float vA[8], vJ[8];
        #pragma unroll
        for (int c = 0; c < 8; ++c) {
            float2 va = unpack2(accA[r >> 1][c]);
            float2 vb = unpack2(accJ[r >> 1][c]);
            vA[c] = (r & 1) ? va.y : va.x;
            vJ[c] = (r & 1) ? vb.y : vb.x;
        }
        oA0 = make_float4(vA[0], vA[1], vA[2], vA[3]);
        oA1 = make_float4(vA[4], vA[5], vA[6], vA[7]);
        oJ0 = make_float4(vJ[0], vJ[1], vJ[2], vJ[3]);
        oJ1 = make_float4(vJ[4], vJ[5], vJ[6], vJ[7]);
        const size_t off = ((size_t)(bN + i) << 6) + dg * 8;
        *(float4*)(g_accA[sp] + off)     = oA0;
        *(float4*)(g_accA[sp] + off + 4) = oA1;
        *(float4*)(g_accJ[sp] + off)     = oJ0;
        *(float4*)(g_accJ[sp] + off + 4) = oJ1;
    }
}

// =====================================================================
// Kernel C: combine splits, normalize, blend, residual
// one thread per 4 output elements
// =====================================================================
__global__ __launch_bounds__(256) void combine_kernel(
    const float* __restrict__ feats, float* __restrict__ out)
{
    const int idx4 = blockIdx.x * blockDim.x + threadIdx.x;   // over B*N*D/4
    const int idx = idx4 * 4;
    const int n = idx >> 6;
    const int d = idx & 63;

    float4 na = make_float4(0.f, 0.f, 0.f, 0.f);
    float4 nj = make_float4(0.f, 0.f, 0.f, 0.f);
    float da = 0.f, dj = 0.f;
    #pragma unroll
    for (int sp = 0; sp < SPLIT; ++sp) {
        const float4 a = *(const float4*)(g_accA[sp] + idx);
        const float4 j = *(const float4*)(g_accJ[sp] + idx);
        na.x += a.x; na.y += a.y; na.z += a.z; na.w += a.w;
        nj.x += j.x; nj.y += j.y; nj.z += j.z; nj.w += j.w;
        da += g_denA[sp][n];
        dj += g_denJ[sp][n];
    }
    const float ra = 1.0f / da;
    const float rj = 1.0f / dj;
    const float4 lA = *(const float4*)&g_lam[d];
    const float4 lJ = *(const float4*)&g_lam[DD + d];
    const float4 f = *(const float4*)(feats + idx);
    float4 o;
    o.x = lA.x * na.x * ra + lJ.x * nj.x * rj + f.x;
    o.y = lA.y * na.y * ra + lJ.y * nj.y * rj + f.y;
    o.z = lA.z * na.z * ra + lJ.z * nj.z * rj + f.z;
    o.w = lA.w * na.w * ra + lJ.w * nj.w * rj + f.w;
    *(float4*)(out + idx) = o;
}

extern "C" void kernel_launch(void* const* d_in, const int* in_sizes, int n_in,
                              void* d_out, int out_size) {
    (void)in_sizes; (void)n_in; (void)out_size;
    const int*   mask_adj      = (const int*)d_in[0];
    const int*   mask_job      = (const int*)d_in[1];
    const int*   bidx          = (const int*)d_in[2];
    const float* feats         = (const float*)d_in[3];
    const float* W             = (const float*)d_in[4];
    const float* attn_src      = (const float*)d_in[5];
    const float* attn_dst      = (const float*)d_in[6];
    const float* lambda_params = (const float*)d_in[7];
    float* out = (float*)d_out;

    prep_kernel<<<BB * NN / 8, 512>>>(feats, W, attn_src, attn_dst, lambda_params);
    attn_split_kernel<<<dim3(NN / TI, BB, SPLIT), 128>>>(mask_adj, mask_job, bidx);
    combine_kernel<<<BB * NN * DD / 4 / 256, 256>>>(feats, out);
}